// round 12
// baseline (speedup 1.0000x reference)
#include <cuda_runtime.h>
#include <cuda_bf16.h>

// LocSE round 12: mma.sync m16n8k16 bf16x3 with FOUR independent tile-groups
// per block (M=64 tiles, 4 warps each) so each SMSP interleaves warps from
// different barrier groups -> scalar phases of one tg overlap MMA phases of
// the others. All scalar X accesses vectorized to 16B (conflict-free at
// 144B row stride). Phase 0: nrm tower + MLP half1 -> out ch0..63 pre-relu
// (+mlp bias) + feats. Phase 1: ang tower + MLP half2 + add + relu.

typedef unsigned int u32;

static __device__ __forceinline__ u32 smaddr(const void* p) {
    u32 a; asm("{ .reg .u64 t; cvta.to.shared.u64 t, %1; cvt.u32.u64 %0, t; }"
               : "=r"(a) : "l"(p));
    return a;
}
static __device__ __forceinline__ u32 bf2_of(float lo, float hi) { // low=lo
    u32 r; asm("cvt.rn.bf16x2.f32 %0, %1, %2;" : "=r"(r) : "f"(hi), "f"(lo));
    return r;
}
static __device__ __forceinline__ float2 f2_of(u32 w) {
    float2 r; r.x = __uint_as_float(w << 16); r.y = __uint_as_float(w & 0xffff0000u);
    return r;
}

#define BARS(id) asm volatile("bar.sync %0, 128;" :: "r"(id) : "memory")

#define LDSM4(r0, r1, r2, r3, addr)                                         \
    asm volatile("ldmatrix.sync.aligned.m8n8.x4.shared.b16 {%0,%1,%2,%3}, [%4];" \
        : "=r"(r0), "=r"(r1), "=r"(r2), "=r"(r3) : "r"(addr))

#define LDSM4T(r0, r1, r2, r3, addr)                                        \
    asm volatile("ldmatrix.sync.aligned.m8n8.x4.trans.shared.b16 {%0,%1,%2,%3}, [%4];" \
        : "=r"(r0), "=r"(r1), "=r"(r2), "=r"(r3) : "r"(addr))

#define MMA16816(d, a0, a1, a2, a3, b0, b1)                                 \
    asm volatile("mma.sync.aligned.m16n8k16.row.col.f32.bf16.bf16.f32 "     \
        "{%0,%1,%2,%3}, {%4,%5,%6,%7}, {%8,%9}, {%0,%1,%2,%3};"             \
        : "+f"((d)[0]), "+f"((d)[1]), "+f"((d)[2]), "+f"((d)[3])            \
        : "r"(a0), "r"(a1), "r"(a2), "r"(a3), "r"(b0), "r"(b1))

// smem byte offsets
#define WM_OFF    110592   // conv weights 0..110592 (2 layers x 3 taps x 2 planes x 9216)
#define MISC_OFF  129024   // fp32 misc: b0 b1 b2 mb w0 (3328 B)
#define SCR_OFF   132352   // channel-sum scratch: 4 tg x 128 floats = 2048
#define X_OFF     134400   // per tg: 19008 (hi 66x144 | lo 66x144); Y fp32 overlay
#define PLOFF     9504     // lo plane offset within a tg's X
#define XSTR      19008
#define SMEM_TOT  (134400 + 4 * 19008)   // 210432

// X row m+1 holds padded row m (m in 0..63); planes hi at +0, lo at +PLOFF.
// Y overlay: fp32, 68-float stride, rows 0..63, at X base (read before next
// build_x; ordering protected by barriers).

static __device__ __forceinline__ void build_x_half(char* xr, const float r[32],
                                                    float s, int m, int h)
{
    char* xh = xr + (m + 1) * 144 + h * 64;
    char* xl = xh + PLOFF;
    u32 hw[16], lw[16];
#pragma unroll
    for (int i = 0; i < 16; i++) {
        float a = r[2 * i] + s, b = r[2 * i + 1] + s;
        u32 hv = bf2_of(a, b);
        float2 hf = f2_of(hv);
        hw[i] = hv;
        lw[i] = bf2_of(a - hf.x, b - hf.y);
    }
#pragma unroll
    for (int i = 0; i < 4; i++) {
        ((uint4*)xh)[i] = make_uint4(hw[4 * i], hw[4 * i + 1], hw[4 * i + 2], hw[4 * i + 3]);
        ((uint4*)xl)[i] = make_uint4(lw[4 * i], lw[4 * i + 1], lw[4 * i + 2], lw[4 * i + 3]);
    }
    const uint4 z = make_uint4(0u, 0u, 0u, 0u);
    if (m == 0) {                         // pad row 0
        char* p = xr + h * 64;
#pragma unroll
        for (int i = 0; i < 4; i++) { ((uint4*)p)[i] = z; ((uint4*)(p + PLOFF))[i] = z; }
    }
    if (m == 63) {                        // pad row 65
        char* p = xr + 65 * 144 + h * 64;
#pragma unroll
        for (int i = 0; i < 4; i++) { ((uint4*)p)[i] = z; ((uint4*)(p + PLOFF))[i] = z; }
    }
}

// acc[nt][4] += X @ W (bf16x3) for this warp's 16 rows (warp w of 4)
template <int NT>
static __device__ __forceinline__ void mma_compute(float acc[8][4],
                                                   u32 xadr, u32 badr,
                                                   int lane, int w)
{
    const int l16 = lane & 15, lhi = lane >> 4;
#pragma unroll
    for (int nt = 0; nt < 8; nt++)
#pragma unroll
        for (int i = 0; i < 4; i++) acc[nt][i] = 0.f;

#pragma unroll 1
    for (int kt = 0; kt < 4; kt++) {
#pragma unroll 1
        for (int tap = 0; tap < NT; tap++) {
            const int tp = (NT == 1) ? 1 : tap;
            u32 ar = xadr + (u32)((w * 16 + l16 + tp) * 144 + kt * 32 + lhi * 16);
            u32 ah0, ah1, ah2, ah3, al0, al1, al2, al3;
            LDSM4(ah0, ah1, ah2, ah3, ar);
            LDSM4(al0, al1, al2, al3, ar + (u32)PLOFF);
            u32 bb = badr + (u32)(tap * 18432 + (kt * 16 + l16) * 144 + lhi * 16);
#pragma unroll
            for (int np = 0; np < 4; np++) {
                u32 b0, b1, b2, b3, c0, c1, c2, c3;
                LDSM4T(b0, b1, b2, b3, bb + np * 32);
                LDSM4T(c0, c1, c2, c3, bb + 9216u + np * 32);
                const int n0 = 2 * np, n1 = 2 * np + 1;
                MMA16816(acc[n0], ah0, ah1, ah2, ah3, b0, b1);
                MMA16816(acc[n1], ah0, ah1, ah2, ah3, b2, b3);
                MMA16816(acc[n0], ah0, ah1, ah2, ah3, c0, c1);
                MMA16816(acc[n1], ah0, ah1, ah2, ah3, c2, c3);
                MMA16816(acc[n0], al0, al1, al2, al3, b0, b1);
                MMA16816(acc[n1], al0, al1, al2, al3, b2, b3);
            }
        }
    }
}

static __device__ __forceinline__ void write_y(char* xr, const float acc[8][4],
                                               int lane, int w)
{
    const int r0 = w * 16 + (lane >> 2);
    const int c = (lane & 3) * 2;
#pragma unroll
    for (int nt = 0; nt < 8; nt++) {
        *(float2*)(xr + (size_t)(r0 * 68 + nt * 8 + c) * 4) =
            make_float2(acc[nt][0], acc[nt][1]);
        *(float2*)(xr + (size_t)((r0 + 8) * 68 + nt * 8 + c) * 4) =
            make_float2(acc[nt][2], acc[nt][3]);
    }
}

// r += relu( conv1d(r + sum_c r, W) + bias ); pad rows forced back to zero
static __device__ __forceinline__ void conv_layer(float r[32], char* xr, u32 xadr,
                                                  u32 badr, const float* bias,
                                                  float* scr, int tg_tid,
                                                  int barid, bool padrow)
{
    const int m = tg_tid & 63, h = tg_tid >> 6;
    const int lane = tg_tid & 31, w = tg_tid >> 5;

    float ps = 0.f;
#pragma unroll
    for (int i = 0; i < 32; i++) ps += r[i];
    scr[h * 64 + m] = ps;
    BARS(barid);
    const float s = scr[m] + scr[64 + m];
    build_x_half(xr, r, s, m, h);
    BARS(barid);

    float acc[8][4];
    mma_compute<3>(acc, xadr, badr, lane, w);

    // recover q = r + s from X (r's registers free across the MMA loop)
    float q[32];
    {
        char* xh = xr + (m + 1) * 144 + h * 64;
        char* xl = xh + PLOFF;
#pragma unroll
        for (int i = 0; i < 4; i++) {
            uint4 hv = ((const uint4*)xh)[i];
            uint4 lv = ((const uint4*)xl)[i];
            float2 a, b;
            a = f2_of(hv.x); b = f2_of(lv.x);
            q[8 * i + 0] = a.x + b.x; q[8 * i + 1] = a.y + b.y;
            a = f2_of(hv.y); b = f2_of(lv.y);
            q[8 * i + 2] = a.x + b.x; q[8 * i + 3] = a.y + b.y;
            a = f2_of(hv.z); b = f2_of(lv.z);
            q[8 * i + 4] = a.x + b.x; q[8 * i + 5] = a.y + b.y;
            a = f2_of(hv.w); b = f2_of(lv.w);
            q[8 * i + 6] = a.x + b.x; q[8 * i + 7] = a.y + b.y;
        }
    }
    BARS(barid);              // everyone done reading X before Y overlay
    write_y(xr, acc, lane, w);
    BARS(barid);
#pragma unroll
    for (int i = 0; i < 8; i++) {
        float4 y = *(const float4*)(xr + (size_t)(m * 68 + h * 32 + i * 4) * 4);
        r[4 * i + 0] = q[4 * i + 0] - s + fmaxf(y.x + bias[h * 32 + 4 * i + 0], 0.f);
        r[4 * i + 1] = q[4 * i + 1] - s + fmaxf(y.y + bias[h * 32 + 4 * i + 1], 0.f);
        r[4 * i + 2] = q[4 * i + 2] - s + fmaxf(y.z + bias[h * 32 + 4 * i + 2], 0.f);
        r[4 * i + 3] = q[4 * i + 3] - s + fmaxf(y.w + bias[h * 32 + 4 * i + 3], 0.f);
    }
    if (padrow) {
#pragma unroll
        for (int i = 0; i < 32; i++) r[i] = 0.f;
    }
    BARS(barid);              // Y fully read before next layer's X overwrites
}

static __device__ __forceinline__ void mlp_half(const float r[32], float am[32],
                                                char* xr, u32 xadr, u32 badr,
                                                int tg_tid, int barid)
{
    const int m = tg_tid & 63, h = tg_tid >> 6;
    const int lane = tg_tid & 31, w = tg_tid >> 5;
    build_x_half(xr, r, 0.f, m, h);
    BARS(barid);
    float acc[8][4];
    mma_compute<1>(acc, xadr, badr, lane, w);
    BARS(barid);
    write_y(xr, acc, lane, w);
    BARS(barid);
#pragma unroll
    for (int i = 0; i < 8; i++) {
        float4 y = *(const float4*)(xr + (size_t)(m * 68 + h * 32 + i * 4) * 4);
        am[4 * i + 0] = y.x; am[4 * i + 1] = y.y;
        am[4 * i + 2] = y.z; am[4 * i + 3] = y.w;
    }
    BARS(barid);
}

__global__ void __launch_bounds__(512, 1)
locse_mma(int phase, const float* __restrict__ pc, const float* __restrict__ feats,
          const float* __restrict__ w0, int w0len, const float* __restrict__ b0,
          const float* __restrict__ w1, const float* __restrict__ b1,
          const float* __restrict__ w2, const float* __restrict__ b2,
          const float* __restrict__ mw, const float* __restrict__ mb,
          float* __restrict__ out, int ngroups, int ntiles)
{
    extern __shared__ __align__(16) char smc[];
    const int tid = threadIdx.x;

    // conv weight tiles: [c][o] row-major, 144B rows, bf16 hi/lo planes
    for (int e = tid; e < 24576; e += 512) {
        int l = e / 12288, rem = e % 12288;
        int k = rem / 4096, c = (rem / 64) % 64, o = rem % 64;
        const float* wl = l ? w2 : w1;
        float wv = wl[(k * 64 + c) * 64 + o];
        __nv_bfloat16 hb = __float2bfloat16(wv);
        float hf = __bfloat162float(hb);
        __nv_bfloat16 lb = __float2bfloat16(wv - hf);
        int base = l * 55296 + k * 18432;
        *(__nv_bfloat16*)(smc + base + c * 144 + o * 2)        = hb;
        *(__nv_bfloat16*)(smc + base + 9216 + c * 144 + o * 2) = lb;
    }
    for (int e = tid; e < 4096; e += 512) {
        int c = e / 64, o = e % 64;
        float wv = mw[(phase * 64 + c) * 64 + o];
        __nv_bfloat16 hb = __float2bfloat16(wv);
        float hf = __bfloat162float(hb);
        __nv_bfloat16 lb = __float2bfloat16(wv - hf);
        *(__nv_bfloat16*)(smc + WM_OFF + c * 144 + o * 2)        = hb;
        *(__nv_bfloat16*)(smc + WM_OFF + 9216 + c * 144 + o * 2) = lb;
    }
    float* msf = (float*)(smc + MISC_OFF);
    if (tid < 64) {
        msf[tid]       = b0[tid];
        msf[64 + tid]  = b1[tid];
        msf[128 + tid] = b2[tid];
        msf[192 + tid] = mb ? mb[tid] : 0.f;
    }
    for (int e = tid; e < w0len; e += 512) msf[256 + e] = w0[e];
    __syncthreads();

    const int tgid = tid >> 7, tg_tid = tid & 127;
    char* xr = smc + X_OFF + tgid * XSTR;
    const u32 xadr = smaddr(xr);
    const u32 bw_adr = smaddr(smc);           // layer l base: + l*55296
    const u32 wm_adr = smaddr(smc + WM_OFF);
    float* scr = (float*)(smc + SCR_OFF) + tgid * 128;
    const int barid = 1 + tgid;
    const int m = tg_tid & 63, h = tg_tid >> 6;
    const int gi = m / 11, prow = m % 11;
    const bool padrow = (prow == 0) || (prow == 10) || (m >= 55);
    const float* b0s = msf;
    const float* b1s = msf + 64;
    const float* b2s = msf + 128;
    const float* mbs = msf + 192;
    const float* w0s = msf + 256;

    for (int tile = blockIdx.x * 4 + tgid; tile < ntiles; tile += gridDim.x * 4) {
        const int gbase = tile * 5;
        float r[32];

        if (phase == 0) {       // nrm layer 0: 1 input channel (2*dx)
            float x[3];
#pragma unroll
            for (int d = 0; d < 3; d++) {
                int row = m + d - 1; float v = 0.f;
                if (row >= 0 && row < 55) {
                    int gg = gbase + row / 11, pr = row % 11;
                    if (pr >= 1 && pr <= 9 && gg < ngroups) {
                        float px = pc[(size_t)gg * 36 + (pr - 1) * 4];
                        float cx = pc[(size_t)gg * 36];
                        v = 2.f * (cx - px);
                    }
                }
                x[d] = v;
            }
#pragma unroll
            for (int i = 0; i < 32; i++) {
                int o = h * 32 + i;
                float a = b0s[o];
                a = fmaf(w0s[o],       x[0], a);
                a = fmaf(w0s[64 + o],  x[1], a);
                a = fmaf(w0s[128 + o], x[2], a);
                r[i] = fmaxf(a, 0.f);
            }
        } else {                // ang layer 0: 3 input channels
            float av[9];
#pragma unroll
            for (int d = 0; d < 3; d++) {
                int row = m + d - 1; float a0 = 0.f, a1 = 0.f, a2 = 0.f;
                if (row >= 0 && row < 55) {
                    int gg = gbase + row / 11, pr = row % 11;
                    if (pr >= 1 && pr <= 9 && gg < ngroups) {
                        const float4 p  = *(const float4*)(pc + (size_t)gg * 36 + (pr - 1) * 4);
                        const float4 cc = *(const float4*)(pc + (size_t)gg * 36);
                        float dx = cc.x - p.x, dy = cc.y - p.y;
                        float s1 = p.x * p.x + p.y * p.y;
                        float nv = (s1 > 0.f) ? sqrtf(s1) : 0.f;
                        float s2 = dx * dx + dy * dy;
                        float dn = (s2 > 0.f) ? sqrtf(s2) : 0.f;
                        float s3 = cc.x * cc.x + cc.y * cc.y + cc.z * cc.z + cc.w * cc.w;
                        float cn = (s3 > 0.f) ? sqrtf(s3) : 0.f;
                        float num = dx * cc.z + dy * cc.w;
                        float den = dn * cn + 1e-8f;
                        float ang = 1.f - fabsf(num / den);
                        float ss = dy + nv + ang;
                        a0 = dy + ss; a1 = nv + ss; a2 = ang + ss;
                    }
                }
                av[d * 3] = a0; av[d * 3 + 1] = a1; av[d * 3 + 2] = a2;
            }
#pragma unroll
            for (int i = 0; i < 32; i++) {
                int o = h * 32 + i;
                float a = b0s[o];
#pragma unroll
                for (int kc = 0; kc < 9; kc++)
                    a = fmaf(w0s[kc * 64 + o], av[kc], a);
                r[i] = fmaxf(a, 0.f);
            }
        }
        if (padrow) {
#pragma unroll
            for (int i = 0; i < 32; i++) r[i] = 0.f;
        }

        conv_layer(r, xr, xadr, bw_adr,         b1s, scr, tg_tid, barid, padrow);
        conv_layer(r, xr, xadr, bw_adr + 55296, b2s, scr, tg_tid, barid, padrow);

        float am[32];
        mlp_half(r, am, xr, xadr, wm_adr, tg_tid, barid);

        if (!padrow) {
            int g = gbase + gi;
            if (g < ngroups) {
                float* og = out + (size_t)g * 1152 + (prow - 1) * 128;
                if (phase == 0) {
#pragma unroll
                    for (int i = 0; i < 32; i++) og[h * 32 + i] = am[i] + mbs[h * 32 + i];
                    const float4* fs = (const float4*)(feats + (size_t)g * 576 + (prow - 1) * 64 + h * 32);
                    float4* od = (float4*)(og + 64 + h * 32);
#pragma unroll
                    for (int q2 = 0; q2 < 8; q2++) od[q2] = fs[q2];
                } else {
#pragma unroll
                    for (int i = 0; i < 32; i++) {
                        int o = h * 32 + i;
                        og[o] = fmaxf(og[o] + am[i], 0.f);
                    }
                }
            }
        }
    }
}

extern "C" void kernel_launch(void* const* d_in, const int* in_sizes, int n_in,
                              void* d_out, int out_size)
{
    const float* pc    = (const float*)d_in[0];
    const float* feats = (const float*)d_in[1];
    // 2..13 = pos_* / rel_* (dead: pos_e/rel_e discarded by the reference)
    const float* nw0 = (const float*)d_in[14];
    const float* nb0 = (const float*)d_in[15];
    const float* nw1 = (const float*)d_in[16];
    const float* nb1 = (const float*)d_in[17];
    const float* nw2 = (const float*)d_in[18];
    const float* nb2 = (const float*)d_in[19];
    const float* aw0 = (const float*)d_in[20];
    const float* ab0 = (const float*)d_in[21];
    const float* aw1 = (const float*)d_in[22];
    const float* ab1 = (const float*)d_in[23];
    const float* aw2 = (const float*)d_in[24];
    const float* ab2 = (const float*)d_in[25];
    const float* mw  = (const float*)d_in[26];
    const float* mb  = (const float*)d_in[27];

    const int ngroups = in_sizes[0] / 36;
    const int ntiles = (ngroups + 4) / 5;

    cudaFuncSetAttribute(locse_mma, cudaFuncAttributeMaxDynamicSharedMemorySize,
                         SMEM_TOT);

    locse_mma<<<148, 512, SMEM_TOT>>>(0, pc, feats, nw0, 192, nb0,
                                      nw1, nb1, nw2, nb2, mw, mb,
                                      (float*)d_out, ngroups, ntiles);
    locse_mma<<<148, 512, SMEM_TOT>>>(1, pc, feats, aw0, 576, ab0,
                                      aw1, ab1, aw2, ab2, mw, nullptr,
                                      (float*)d_out, ngroups, ntiles);
}

// round 16
// speedup vs baseline: 1.1819x; 1.1819x over previous
#include <cuda_runtime.h>
#include <cuda_bf16.h>

// LocSE round 13: warp-specialized mma.sync bf16x3.
// 384 threads: warps 0-3 scalar tile-A (thread=row, M=128), warps 4-7 scalar
// tile-B, warps 8-11 MMA pool (mt=2: 32 rows/warp). Producer/consumer via
// named barriers: scalar builds X -> arrive(ready); pool sync(ready), MMAs,
// write_y, arrive(done); scalar sync(done), updates r (r stays in registers).
// Pool alternates tiles A,B each layer so the tensor pipe stays fed while
// scalar warps run prologue/epilogue/build phases.
// Phase 0: nrm tower + MLP half1 -> out ch0..63 pre-relu (+mlp bias) + feats.
// Phase 1: ang tower + MLP half2 + add + relu.

typedef unsigned int u32;

static __device__ __forceinline__ u32 smaddr(const void* p) {
    u32 a; asm("{ .reg .u64 t; cvta.to.shared.u64 t, %1; cvt.u32.u64 %0, t; }"
               : "=r"(a) : "l"(p));
    return a;
}
static __device__ __forceinline__ u32 bf2_of(float lo, float hi) { // low=lo
    u32 r; asm("cvt.rn.bf16x2.f32 %0, %1, %2;" : "=r"(r) : "f"(hi), "f"(lo));
    return r;
}
static __device__ __forceinline__ float2 f2_of(u32 w) {
    float2 r; r.x = __uint_as_float(w << 16); r.y = __uint_as_float(w & 0xffff0000u);
    return r;
}

#define BAR_SYNC(id, n)   asm volatile("bar.sync %0, %1;"   :: "r"(id), "r"(n) : "memory")
#define BAR_ARRIVE(id, n) asm volatile("bar.arrive %0, %1;" :: "r"(id), "r"(n) : "memory")

#define LDSM4(r0, r1, r2, r3, addr)                                         \
    asm volatile("ldmatrix.sync.aligned.m8n8.x4.shared.b16 {%0,%1,%2,%3}, [%4];" \
        : "=r"(r0), "=r"(r1), "=r"(r2), "=r"(r3) : "r"(addr))

#define LDSM4T(r0, r1, r2, r3, addr)                                        \
    asm volatile("ldmatrix.sync.aligned.m8n8.x4.trans.shared.b16 {%0,%1,%2,%3}, [%4];" \
        : "=r"(r0), "=r"(r1), "=r"(r2), "=r"(r3) : "r"(addr))

#define MMA16816(d, a0, a1, a2, a3, b0, b1)                                 \
    asm volatile("mma.sync.aligned.m16n8k16.row.col.f32.bf16.bf16.f32 "     \
        "{%0,%1,%2,%3}, {%4,%5,%6,%7}, {%8,%9}, {%0,%1,%2,%3};"             \
        : "+f"((d)[0]), "+f"((d)[1]), "+f"((d)[2]), "+f"((d)[3])            \
        : "r"(a0), "r"(a1), "r"(a2), "r"(a3), "r"(b0), "r"(b1))

// smem byte offsets
#define WM_OFF    110592   // conv weights 0..110592 (2 layers x 3 taps x 2 planes x 9216)
#define MISC_OFF  129024   // fp32 misc: b0 b1 b2 mb w0 (3328 B)
#define XA_OFF    132352   // tile A X: hi 130x144 | lo 130x144 = 37440; Y fp32 overlay
#define XSTR      37440
#define PLOFF     18720
#define SMEM_TOT  (132352 + 2 * 37440)   // 207232

// X row m+1 holds padded row m (m 0..127); pad rows 0 and 129.
// Y overlay: fp32, 68-float stride, rows 0..127, at X base (barrier-ordered).

// Named barriers: 1=readyA 2=doneA 3=readyB 4=doneB (256 each: 128 arrive +
// 128 sync), 5=pool-internal (128), 6=tgA-internal (128), 7=tgB-internal (128).

static __device__ __forceinline__ void build_x(char* xr, const float r[64],
                                               float s, int m)
{
    char* xh = xr + (m + 1) * 144;
    char* xl = xh + PLOFF;
#pragma unroll
    for (int i = 0; i < 8; i++) {
        u32 h[4], l[4];
#pragma unroll
        for (int j = 0; j < 4; j++) {
            float a = r[8 * i + 2 * j] + s, b = r[8 * i + 2 * j + 1] + s;
            u32 hv = bf2_of(a, b);
            float2 hf = f2_of(hv);
            h[j] = hv;
            l[j] = bf2_of(a - hf.x, b - hf.y);
        }
        ((uint4*)xh)[i] = make_uint4(h[0], h[1], h[2], h[3]);
        ((uint4*)xl)[i] = make_uint4(l[0], l[1], l[2], l[3]);
    }
    const uint4 z = make_uint4(0u, 0u, 0u, 0u);
    if (m == 0) {                         // pad row 0
#pragma unroll
        for (int i = 0; i < 8; i++) { ((uint4*)xr)[i] = z; ((uint4*)(xr + PLOFF))[i] = z; }
    }
    if (m == 127) {                       // pad row 129
        char* p = xr + 129 * 144;
#pragma unroll
        for (int i = 0; i < 8; i++) { ((uint4*)p)[i] = z; ((uint4*)(p + PLOFF))[i] = z; }
    }
}

// Pool-side GEMM: acc[mt][nt][4] for this warp's 32 rows (pw*32..+31), bf16x3.
template <int NT>
static __device__ __forceinline__ void mma_pool(float acc[2][8][4],
                                                u32 xadr, u32 badr,
                                                int lane, int pw)
{
    const int l16 = lane & 15, lhi = lane >> 4;
#pragma unroll
    for (int mt = 0; mt < 2; mt++)
#pragma unroll
        for (int nt = 0; nt < 8; nt++)
#pragma unroll
            for (int i = 0; i < 4; i++) acc[mt][nt][i] = 0.f;

#pragma unroll 1
    for (int kt = 0; kt < 4; kt++) {
#pragma unroll 1
        for (int tap = 0; tap < NT; tap++) {
            const int tp = (NT == 1) ? 1 : tap;
            u32 ar = xadr + (u32)((pw * 32 + l16 + tp) * 144 + kt * 32 + lhi * 16);
            u32 ah0, ah1, ah2, ah3, al0, al1, al2, al3;
            LDSM4(ah0, ah1, ah2, ah3, ar);
            LDSM4(al0, al1, al2, al3, ar + (u32)PLOFF);
            u32 ar1 = ar + 16u * 144u;
            u32 dh0, dh1, dh2, dh3, dl0, dl1, dl2, dl3;
            LDSM4(dh0, dh1, dh2, dh3, ar1);
            LDSM4(dl0, dl1, dl2, dl3, ar1 + (u32)PLOFF);
            u32 bb = badr + (u32)(tap * 18432 + (kt * 16 + l16) * 144 + lhi * 16);
#pragma unroll
            for (int np = 0; np < 4; np++) {
                u32 b0, b1, b2, b3, c0, c1, c2, c3;
                LDSM4T(b0, b1, b2, b3, bb + np * 32);
                LDSM4T(c0, c1, c2, c3, bb + 9216u + np * 32);
                const int n0 = 2 * np, n1 = 2 * np + 1;
                MMA16816(acc[0][n0], ah0, ah1, ah2, ah3, b0, b1);
                MMA16816(acc[1][n0], dh0, dh1, dh2, dh3, b0, b1);
                MMA16816(acc[0][n1], ah0, ah1, ah2, ah3, b2, b3);
                MMA16816(acc[1][n1], dh0, dh1, dh2, dh3, b2, b3);
                MMA16816(acc[0][n0], ah0, ah1, ah2, ah3, c0, c1);
                MMA16816(acc[1][n0], dh0, dh1, dh2, dh3, c0, c1);
                MMA16816(acc[0][n1], ah0, ah1, ah2, ah3, c2, c3);
                MMA16816(acc[1][n1], dh0, dh1, dh2, dh3, c2, c3);
                MMA16816(acc[0][n0], al0, al1, al2, al3, b0, b1);
                MMA16816(acc[1][n0], dl0, dl1, dl2, dl3, b0, b1);
                MMA16816(acc[0][n1], al0, al1, al2, al3, b2, b3);
                MMA16816(acc[1][n1], dl0, dl1, dl2, dl3, b2, b3);
            }
        }
    }
}

static __device__ __forceinline__ void write_y(char* xr, const float acc[2][8][4],
                                               int lane, int pw)
{
    const int c = (lane & 3) * 2;
#pragma unroll
    for (int mt = 0; mt < 2; mt++) {
        const int r0 = pw * 32 + mt * 16 + (lane >> 2);
#pragma unroll
        for (int nt = 0; nt < 8; nt++) {
            *(float2*)(xr + (size_t)(r0 * 68 + nt * 8 + c) * 4) =
                make_float2(acc[mt][nt][0], acc[mt][nt][1]);
            *(float2*)(xr + (size_t)((r0 + 8) * 68 + nt * 8 + c) * 4) =
                make_float2(acc[mt][nt][2], acc[mt][nt][3]);
        }
    }
}

__global__ void __launch_bounds__(384, 1)
locse_ws(int phase, const float* __restrict__ pc, const float* __restrict__ feats,
         const float* __restrict__ w0, int w0len, const float* __restrict__ b0,
         const float* __restrict__ w1, const float* __restrict__ b1,
         const float* __restrict__ w2, const float* __restrict__ b2,
         const float* __restrict__ mw, const float* __restrict__ mb,
         float* __restrict__ out, int ngroups, int ntiles, int nit)
{
    extern __shared__ __align__(16) char smc[];
    const int tid = threadIdx.x;

    // conv weight tiles: [c][o] row-major, 144B rows, bf16 hi/lo planes
    for (int e = tid; e < 24576; e += 384) {
        int l = e / 12288, rem = e % 12288;
        int k = rem / 4096, c = (rem / 64) % 64, o = rem % 64;
        const float* wl = l ? w2 : w1;
        float wv = wl[(k * 64 + c) * 64 + o];
        __nv_bfloat16 hb = __float2bfloat16(wv);
        float hf = __bfloat162float(hb);
        __nv_bfloat16 lb = __float2bfloat16(wv - hf);
        int base = l * 55296 + k * 18432;
        *(__nv_bfloat16*)(smc + base + c * 144 + o * 2)        = hb;
        *(__nv_bfloat16*)(smc + base + 9216 + c * 144 + o * 2) = lb;
    }
    for (int e = tid; e < 4096; e += 384) {
        int c = e / 64, o = e % 64;
        float wv = mw[(phase * 64 + c) * 64 + o];
        __nv_bfloat16 hb = __float2bfloat16(wv);
        float hf = __bfloat162float(hb);
        __nv_bfloat16 lb = __float2bfloat16(wv - hf);
        *(__nv_bfloat16*)(smc + WM_OFF + c * 144 + o * 2)        = hb;
        *(__nv_bfloat16*)(smc + WM_OFF + 9216 + c * 144 + o * 2) = lb;
    }
    float* msf = (float*)(smc + MISC_OFF);
    if (tid < 64) {
        msf[tid]       = b0[tid];
        msf[64 + tid]  = b1[tid];
        msf[128 + tid] = b2[tid];
        msf[192 + tid] = mb ? mb[tid] : 0.f;
    }
    for (int e = tid; e < w0len; e += 384) msf[256 + e] = w0[e];
    __syncthreads();

    const int wid = tid >> 5;

    if (wid >= 8) {
        // ------------------- MMA pool (warps 8..11) -------------------
        const int lane = tid & 31, pw = wid - 8;
        char* xrA = smc + XA_OFF;
        char* xrB = xrA + XSTR;
        const u32 xa = smaddr(xrA), xb = smaddr(xrB);
        const u32 bw = smaddr(smc), wm = smaddr(smc + WM_OFF);
        for (int it = 0; it < nit; it++) {
#pragma unroll 1
            for (int L = 0; L < 3; L++) {
                float acc[2][8][4];
                // tile A
                BAR_SYNC(1, 256);
                if (L < 2) mma_pool<3>(acc, xa, bw + (u32)(L * 55296), lane, pw);
                else       mma_pool<1>(acc, xa, wm, lane, pw);
                BAR_SYNC(5, 128);          // pool done reading X_A
                write_y(xrA, acc, lane, pw);
                BAR_ARRIVE(2, 256);
                // tile B
                BAR_SYNC(3, 256);
                if (L < 2) mma_pool<3>(acc, xb, bw + (u32)(L * 55296), lane, pw);
                else       mma_pool<1>(acc, xb, wm, lane, pw);
                BAR_SYNC(5, 128);          // pool done reading X_B
                write_y(xrB, acc, lane, pw);
                BAR_ARRIVE(4, 256);
            }
        }
    } else {
        // ------------------- scalar groups (warps 0..7) -------------------
        const int tg = wid >> 2;           // 0 = tile A, 1 = tile B
        const int m = tid & 127;           // this thread's row
        char* xr = smc + XA_OFF + tg * XSTR;
        const int rdy = 1 + 2 * tg, dn = 2 + 2 * tg, ib = 6 + tg;
        const int gi = m / 11, prow = m % 11;
        const bool padrow = (prow == 0) || (prow == 10) || (m >= 121);
        const float* b0s = msf;
        const float* b1s = msf + 64;
        const float* b2s = msf + 128;
        const float* mbs = msf + 192;
        const float* w0s = msf + 256;

        for (int it = 0; it < nit; it++) {
            const int tile = blockIdx.x * 2 + tg + it * gridDim.x * 2;
            const bool live = (tile < ntiles);
            const int gbase = tile * 11;
            float r[64];

            // ---- prologue: layer 0 ----
            if (phase == 0) {
                float x[3];
#pragma unroll
                for (int d = 0; d < 3; d++) {
                    int row = m + d - 1; float v = 0.f;
                    if (live && row >= 0 && row < 121) {
                        int gg = gbase + row / 11, pr = row % 11;
                        if (pr >= 1 && pr <= 9 && gg < ngroups) {
                            float px = pc[(size_t)gg * 36 + (pr - 1) * 4];
                            float cx = pc[(size_t)gg * 36];
                            v = 2.f * (cx - px);
                        }
                    }
                    x[d] = v;
                }
#pragma unroll
                for (int o = 0; o < 64; o++) {
                    float a = b0s[o];
                    a = fmaf(w0s[o],       x[0], a);
                    a = fmaf(w0s[64 + o],  x[1], a);
                    a = fmaf(w0s[128 + o], x[2], a);
                    r[o] = fmaxf(a, 0.f);
                }
            } else {
                float av[9];
#pragma unroll
                for (int d = 0; d < 3; d++) {
                    int row = m + d - 1; float a0 = 0.f, a1 = 0.f, a2 = 0.f;
                    if (live && row >= 0 && row < 121) {
                        int gg = gbase + row / 11, pr = row % 11;
                        if (pr >= 1 && pr <= 9 && gg < ngroups) {
                            const float4 p  = *(const float4*)(pc + (size_t)gg * 36 + (pr - 1) * 4);
                            const float4 cc = *(const float4*)(pc + (size_t)gg * 36);
                            float dx = cc.x - p.x, dy = cc.y - p.y;
                            float s1 = p.x * p.x + p.y * p.y;
                            float nv = (s1 > 0.f) ? sqrtf(s1) : 0.f;
                            float s2 = dx * dx + dy * dy;
                            float dn2 = (s2 > 0.f) ? sqrtf(s2) : 0.f;
                            float s3 = cc.x * cc.x + cc.y * cc.y + cc.z * cc.z + cc.w * cc.w;
                            float cn = (s3 > 0.f) ? sqrtf(s3) : 0.f;
                            float num = dx * cc.z + dy * cc.w;
                            float den = dn2 * cn + 1e-8f;
                            float ang = 1.f - fabsf(num / den);
                            float ss = dy + nv + ang;
                            a0 = dy + ss; a1 = nv + ss; a2 = ang + ss;
                        }
                    }
                    av[d * 3] = a0; av[d * 3 + 1] = a1; av[d * 3 + 2] = a2;
                }
#pragma unroll
                for (int o = 0; o < 64; o++) {
                    float a = b0s[o];
#pragma unroll
                    for (int kc = 0; kc < 9; kc++)
                        a = fmaf(w0s[kc * 64 + o], av[kc], a);
                    r[o] = fmaxf(a, 0.f);
                }
            }
            if (padrow) {
#pragma unroll
                for (int o = 0; o < 64; o++) r[o] = 0.f;
            }

            // ---- conv layers 1 and 2 ----
#pragma unroll 1
            for (int L = 0; L < 2; L++) {
                const float* bias = L ? b2s : b1s;
                float s = 0.f;
#pragma unroll
                for (int o = 0; o < 64; o++) s += r[o];
                build_x(xr, r, s, m);
                BAR_ARRIVE(rdy, 256);
                BAR_SYNC(dn, 256);
#pragma unroll
                for (int i = 0; i < 16; i++) {
                    float4 y = *(const float4*)(xr + (size_t)(m * 68 + i * 4) * 4);
                    r[4 * i + 0] += fmaxf(y.x + bias[4 * i + 0], 0.f);
                    r[4 * i + 1] += fmaxf(y.y + bias[4 * i + 1], 0.f);
                    r[4 * i + 2] += fmaxf(y.z + bias[4 * i + 2], 0.f);
                    r[4 * i + 3] += fmaxf(y.w + bias[4 * i + 3], 0.f);
                }
                if (padrow) {
#pragma unroll
                    for (int o = 0; o < 64; o++) r[o] = 0.f;
                }
                BAR_SYNC(ib, 128);   // Y reads done before next X build
            }

            // ---- MLP half ----
            build_x(xr, r, 0.f, m);
            BAR_ARRIVE(rdy, 256);
            BAR_SYNC(dn, 256);
            {
                const int g = gbase + gi;
                const bool wr = live && !padrow && (g < ngroups);
                float* og = out + (size_t)g * 1152 + (prow - 1) * 128;
                if (phase == 0) {
                    if (wr) {
#pragma unroll
                        for (int i = 0; i < 16; i++) {
                            float4 y = *(const float4*)(xr + (size_t)(m * 68 + i * 4) * 4);
                            y.x += mbs[4 * i + 0]; y.y += mbs[4 * i + 1];
                            y.z += mbs[4 * i + 2]; y.w += mbs[4 * i + 3];
                            *(float4*)(og + 4 * i) = y;
                        }
                        const float4* fs = (const float4*)(feats + (size_t)g * 576 + (prow - 1) * 64);
                        float4* od = (float4*)(og + 64);
#pragma unroll
                        for (int q2 = 0; q2 < 16; q2++) od[q2] = fs[q2];
                    }
                } else {
                    if (wr) {
#pragma unroll
                        for (int i = 0; i < 16; i++) {
                            float4 y = *(const float4*)(xr + (size_t)(m * 68 + i * 4) * 4);
                            float4 o4 = *(const float4*)(og + 4 * i);
                            o4.x = fmaxf(o4.x + y.x, 0.f);
                            o4.y = fmaxf(o4.y + y.y, 0.f);
                            o4.z = fmaxf(o4.z + y.z, 0.f);
                            o4.w = fmaxf(o4.w + y.w, 0.f);
                            *(float4*)(og + 4 * i) = o4;
                        }
                    }
                }
            }
            BAR_SYNC(ib, 128);       // Y reads done before next tile's X build
        }
    }
}

extern "C" void kernel_launch(void* const* d_in, const int* in_sizes, int n_in,
                              void* d_out, int out_size)
{
    const float* pc    = (const float*)d_in[0];
    const float* feats = (const float*)d_in[1];
    // 2..13 = pos_* / rel_* (dead: pos_e/rel_e discarded by the reference)
    const float* nw0 = (const float*)d_in[14];
    const float* nb0 = (const float*)d_in[15];
    const float* nw1 = (const float*)d_in[16];
    const float* nb1 = (const float*)d_in[17];
    const float* nw2 = (const float*)d_in[18];
    const float* nb2 = (const float*)d_in[19];
    const float* aw0 = (const float*)d_in[20];
    const float* ab0 = (const float*)d_in[21];
    const float* aw1 = (const float*)d_in[22];
    const float* ab1 = (const float*)d_in[23];
    const float* aw2 = (const float*)d_in[24];
    const float* ab2 = (const float*)d_in[25];
    const float* mw  = (const float*)d_in[26];
    const float* mb  = (const float*)d_in[27];

    const int ngroups = in_sizes[0] / 36;
    const int ntiles = (ngroups + 10) / 11;
    const int grid = 148;
    const int nit = (ntiles + 2 * grid - 1) / (2 * grid);

    cudaFuncSetAttribute(locse_ws, cudaFuncAttributeMaxDynamicSharedMemorySize,
                         SMEM_TOT);

    locse_ws<<<grid, 384, SMEM_TOT>>>(0, pc, feats, nw0, 192, nb0,
                                      nw1, nb1, nw2, nb2, mw, mb,
                                      (float*)d_out, ngroups, ntiles, nit);
    locse_ws<<<grid, 384, SMEM_TOT>>>(1, pc, feats, aw0, 576, ab0,
                                      aw1, ab1, aw2, ab2, mw, nullptr,
                                      (float*)d_out, ngroups, ntiles, nit);
}

// round 17
// speedup vs baseline: 1.1973x; 1.0130x over previous
#include <cuda_runtime.h>
#include <cuda_bf16.h>

// LocSE round 17: warp-specialized mma.sync bf16x3, TWO pool warps per SMSP.
// 512 threads: warps 0-3 scalar tile-A (thread=row, M=128), warps 4-7 scalar
// tile-B, warps 8-15 MMA pool (mt=1: 16 rows/warp, 2 pool warps per SMSP so
// their MMA issue interleaves and fills the tensor pipe).
// Producer/consumer via named barriers: scalar builds X -> arrive(ready);
// pool sync(ready), MMAs, write_y, arrive(done); scalar sync(done), updates r.
// Phase 0: nrm tower + MLP half1 -> out ch0..63 pre-relu (+mlp bias) + feats.
// Phase 1: ang tower + MLP half2 + add + relu.

typedef unsigned int u32;

static __device__ __forceinline__ u32 smaddr(const void* p) {
    u32 a; asm("{ .reg .u64 t; cvta.to.shared.u64 t, %1; cvt.u32.u64 %0, t; }"
               : "=r"(a) : "l"(p));
    return a;
}
static __device__ __forceinline__ u32 bf2_of(float lo, float hi) { // low=lo
    u32 r; asm("cvt.rn.bf16x2.f32 %0, %1, %2;" : "=r"(r) : "f"(hi), "f"(lo));
    return r;
}
static __device__ __forceinline__ float2 f2_of(u32 w) {
    float2 r; r.x = __uint_as_float(w << 16); r.y = __uint_as_float(w & 0xffff0000u);
    return r;
}

#define BAR_SYNC(id, n)   asm volatile("bar.sync %0, %1;"   :: "r"(id), "r"(n) : "memory")
#define BAR_ARRIVE(id, n) asm volatile("bar.arrive %0, %1;" :: "r"(id), "r"(n) : "memory")

#define LDSM4(r0, r1, r2, r3, addr)                                         \
    asm volatile("ldmatrix.sync.aligned.m8n8.x4.shared.b16 {%0,%1,%2,%3}, [%4];" \
        : "=r"(r0), "=r"(r1), "=r"(r2), "=r"(r3) : "r"(addr))

#define LDSM4T(r0, r1, r2, r3, addr)                                        \
    asm volatile("ldmatrix.sync.aligned.m8n8.x4.trans.shared.b16 {%0,%1,%2,%3}, [%4];" \
        : "=r"(r0), "=r"(r1), "=r"(r2), "=r"(r3) : "r"(addr))

#define MMA16816(d, a0, a1, a2, a3, b0, b1)                                 \
    asm volatile("mma.sync.aligned.m16n8k16.row.col.f32.bf16.bf16.f32 "     \
        "{%0,%1,%2,%3}, {%4,%5,%6,%7}, {%8,%9}, {%0,%1,%2,%3};"             \
        : "+f"((d)[0]), "+f"((d)[1]), "+f"((d)[2]), "+f"((d)[3])            \
        : "r"(a0), "r"(a1), "r"(a2), "r"(a3), "r"(b0), "r"(b1))

// smem byte offsets
#define WM_OFF    110592   // conv weights 0..110592 (2 layers x 3 taps x 2 planes x 9216)
#define MISC_OFF  129024   // fp32 misc: b0 b1 b2 mb w0 (3328 B)
#define XA_OFF    132352   // tile A X: hi 130x144 | lo 130x144 = 37440; Y fp32 overlay
#define XSTR      37440
#define PLOFF     18720
#define SMEM_TOT  (132352 + 2 * 37440)   // 207232

// X row m+1 holds padded row m (m 0..127); pad rows 0 and 129.
// Y overlay: fp32, 68-float stride, rows 0..127, at X base (barrier-ordered).

// Named barriers: 1=readyA 2=doneA 3=readyB 4=doneB (384 each: 128 scalar +
// 256 pool), 5=pool-internal (256), 6=tgA-internal (128), 7=tgB-internal (128).

static __device__ __forceinline__ void build_x(char* xr, const float r[64],
                                               float s, int m)
{
    char* xh = xr + (m + 1) * 144;
    char* xl = xh + PLOFF;
#pragma unroll
    for (int i = 0; i < 8; i++) {
        u32 h[4], l[4];
#pragma unroll
        for (int j = 0; j < 4; j++) {
            float a = r[8 * i + 2 * j] + s, b = r[8 * i + 2 * j + 1] + s;
            u32 hv = bf2_of(a, b);
            float2 hf = f2_of(hv);
            h[j] = hv;
            l[j] = bf2_of(a - hf.x, b - hf.y);
        }
        ((uint4*)xh)[i] = make_uint4(h[0], h[1], h[2], h[3]);
        ((uint4*)xl)[i] = make_uint4(l[0], l[1], l[2], l[3]);
    }
    const uint4 z = make_uint4(0u, 0u, 0u, 0u);
    if (m == 0) {                         // pad row 0
#pragma unroll
        for (int i = 0; i < 8; i++) { ((uint4*)xr)[i] = z; ((uint4*)(xr + PLOFF))[i] = z; }
    }
    if (m == 127) {                       // pad row 129
        char* p = xr + 129 * 144;
#pragma unroll
        for (int i = 0; i < 8; i++) { ((uint4*)p)[i] = z; ((uint4*)(p + PLOFF))[i] = z; }
    }
}

// Pool-side GEMM, mt=1: acc[nt][4] for this warp's 16 rows (pw*16..+15).
template <int NT>
static __device__ __forceinline__ void mma_pool(float acc[8][4],
                                                u32 xadr, u32 badr,
                                                int lane, int pw)
{
    const int l16 = lane & 15, lhi = lane >> 4;
#pragma unroll
    for (int nt = 0; nt < 8; nt++)
#pragma unroll
        for (int i = 0; i < 4; i++) acc[nt][i] = 0.f;

#pragma unroll 1
    for (int kt = 0; kt < 4; kt++) {
#pragma unroll 1
        for (int tap = 0; tap < NT; tap++) {
            const int tp = (NT == 1) ? 1 : tap;
            u32 ar = xadr + (u32)((pw * 16 + l16 + tp) * 144 + kt * 32 + lhi * 16);
            u32 ah0, ah1, ah2, ah3, al0, al1, al2, al3;
            LDSM4(ah0, ah1, ah2, ah3, ar);
            LDSM4(al0, al1, al2, al3, ar + (u32)PLOFF);
            u32 bb = badr + (u32)(tap * 18432 + (kt * 16 + l16) * 144 + lhi * 16);
#pragma unroll
            for (int np = 0; np < 4; np++) {
                u32 b0, b1, b2, b3, c0, c1, c2, c3;
                LDSM4T(b0, b1, b2, b3, bb + np * 32);
                LDSM4T(c0, c1, c2, c3, bb + 9216u + np * 32);
                const int n0 = 2 * np, n1 = 2 * np + 1;
                MMA16816(acc[n0], ah0, ah1, ah2, ah3, b0, b1);
                MMA16816(acc[n1], ah0, ah1, ah2, ah3, b2, b3);
                MMA16816(acc[n0], ah0, ah1, ah2, ah3, c0, c1);
                MMA16816(acc[n1], ah0, ah1, ah2, ah3, c2, c3);
                MMA16816(acc[n0], al0, al1, al2, al3, b0, b1);
                MMA16816(acc[n1], al0, al1, al2, al3, b2, b3);
            }
        }
    }
}

static __device__ __forceinline__ void write_y(char* xr, const float acc[8][4],
                                               int lane, int pw)
{
    const int c = (lane & 3) * 2;
    const int r0 = pw * 16 + (lane >> 2);
#pragma unroll
    for (int nt = 0; nt < 8; nt++) {
        *(float2*)(xr + (size_t)(r0 * 68 + nt * 8 + c) * 4) =
            make_float2(acc[nt][0], acc[nt][1]);
        *(float2*)(xr + (size_t)((r0 + 8) * 68 + nt * 8 + c) * 4) =
            make_float2(acc[nt][2], acc[nt][3]);
    }
}

__global__ void __launch_bounds__(512, 1)
locse_ws(int phase, const float* __restrict__ pc, const float* __restrict__ feats,
         const float* __restrict__ w0, int w0len, const float* __restrict__ b0,
         const float* __restrict__ w1, const float* __restrict__ b1,
         const float* __restrict__ w2, const float* __restrict__ b2,
         const float* __restrict__ mw, const float* __restrict__ mb,
         float* __restrict__ out, int ngroups, int ntiles, int nit)
{
    extern __shared__ __align__(16) char smc[];
    const int tid = threadIdx.x;

    // conv weight tiles: [c][o] row-major, 144B rows, bf16 hi/lo planes
    for (int e = tid; e < 24576; e += 512) {
        int l = e / 12288, rem = e % 12288;
        int k = rem / 4096, c = (rem / 64) % 64, o = rem % 64;
        const float* wl = l ? w2 : w1;
        float wv = wl[(k * 64 + c) * 64 + o];
        __nv_bfloat16 hb = __float2bfloat16(wv);
        float hf = __bfloat162float(hb);
        __nv_bfloat16 lb = __float2bfloat16(wv - hf);
        int base = l * 55296 + k * 18432;
        *(__nv_bfloat16*)(smc + base + c * 144 + o * 2)        = hb;
        *(__nv_bfloat16*)(smc + base + 9216 + c * 144 + o * 2) = lb;
    }
    for (int e = tid; e < 4096; e += 512) {
        int c = e / 64, o = e % 64;
        float wv = mw[(phase * 64 + c) * 64 + o];
        __nv_bfloat16 hb = __float2bfloat16(wv);
        float hf = __bfloat162float(hb);
        __nv_bfloat16 lb = __float2bfloat16(wv - hf);
        *(__nv_bfloat16*)(smc + WM_OFF + c * 144 + o * 2)        = hb;
        *(__nv_bfloat16*)(smc + WM_OFF + 9216 + c * 144 + o * 2) = lb;
    }
    float* msf = (float*)(smc + MISC_OFF);
    if (tid < 64) {
        msf[tid]       = b0[tid];
        msf[64 + tid]  = b1[tid];
        msf[128 + tid] = b2[tid];
        msf[192 + tid] = mb ? mb[tid] : 0.f;
    }
    for (int e = tid; e < w0len; e += 512) msf[256 + e] = w0[e];
    __syncthreads();

    const int wid = tid >> 5;

    if (wid >= 8) {
        // ------------------- MMA pool (warps 8..15, mt=1) -------------------
        const int lane = tid & 31, pw = wid - 8;
        char* xrA = smc + XA_OFF;
        char* xrB = xrA + XSTR;
        const u32 xa = smaddr(xrA), xb = smaddr(xrB);
        const u32 bw = smaddr(smc), wm = smaddr(smc + WM_OFF);
        for (int it = 0; it < nit; it++) {
#pragma unroll 1
            for (int L = 0; L < 3; L++) {
                float acc[8][4];
                // tile A
                BAR_SYNC(1, 384);
                if (L < 2) mma_pool<3>(acc, xa, bw + (u32)(L * 55296), lane, pw);
                else       mma_pool<1>(acc, xa, wm, lane, pw);
                BAR_SYNC(5, 256);          // pool done reading X_A
                write_y(xrA, acc, lane, pw);
                BAR_ARRIVE(2, 384);
                // tile B
                BAR_SYNC(3, 384);
                if (L < 2) mma_pool<3>(acc, xb, bw + (u32)(L * 55296), lane, pw);
                else       mma_pool<1>(acc, xb, wm, lane, pw);
                BAR_SYNC(5, 256);          // pool done reading X_B
                write_y(xrB, acc, lane, pw);
                BAR_ARRIVE(4, 384);
            }
        }
    } else {
        // ------------------- scalar groups (warps 0..7) -------------------
        const int tg = wid >> 2;           // 0 = tile A, 1 = tile B
        const int m = tid & 127;           // this thread's row
        char* xr = smc + XA_OFF + tg * XSTR;
        const int rdy = 1 + 2 * tg, dn = 2 + 2 * tg, ib = 6 + tg;
        const int gi = m / 11, prow = m % 11;
        const bool padrow = (prow == 0) || (prow == 10) || (m >= 121);
        const float* b0s = msf;
        const float* b1s = msf + 64;
        const float* b2s = msf + 128;
        const float* mbs = msf + 192;
        const float* w0s = msf + 256;

        for (int it = 0; it < nit; it++) {
            const int tile = blockIdx.x * 2 + tg + it * gridDim.x * 2;
            const bool live = (tile < ntiles);
            const int gbase = tile * 11;
            float r[64];

            // ---- prologue: layer 0 ----
            if (phase == 0) {
                float x[3];
#pragma unroll
                for (int d = 0; d < 3; d++) {
                    int row = m + d - 1; float v = 0.f;
                    if (live && row >= 0 && row < 121) {
                        int gg = gbase + row / 11, pr = row % 11;
                        if (pr >= 1 && pr <= 9 && gg < ngroups) {
                            float px = pc[(size_t)gg * 36 + (pr - 1) * 4];
                            float cx = pc[(size_t)gg * 36];
                            v = 2.f * (cx - px);
                        }
                    }
                    x[d] = v;
                }
#pragma unroll
                for (int o = 0; o < 64; o++) {
                    float a = b0s[o];
                    a = fmaf(w0s[o],       x[0], a);
                    a = fmaf(w0s[64 + o],  x[1], a);
                    a = fmaf(w0s[128 + o], x[2], a);
                    r[o] = fmaxf(a, 0.f);
                }
            } else {
                float av[9];
#pragma unroll
                for (int d = 0; d < 3; d++) {
                    int row = m + d - 1; float a0 = 0.f, a1 = 0.f, a2 = 0.f;
                    if (live && row >= 0 && row < 121) {
                        int gg = gbase + row / 11, pr = row % 11;
                        if (pr >= 1 && pr <= 9 && gg < ngroups) {
                            const float4 p  = *(const float4*)(pc + (size_t)gg * 36 + (pr - 1) * 4);
                            const float4 cc = *(const float4*)(pc + (size_t)gg * 36);
                            float dx = cc.x - p.x, dy = cc.y - p.y;
                            float s1 = p.x * p.x + p.y * p.y;
                            float nv = (s1 > 0.f) ? sqrtf(s1) : 0.f;
                            float s2 = dx * dx + dy * dy;
                            float dn2 = (s2 > 0.f) ? sqrtf(s2) : 0.f;
                            float s3 = cc.x * cc.x + cc.y * cc.y + cc.z * cc.z + cc.w * cc.w;
                            float cn = (s3 > 0.f) ? sqrtf(s3) : 0.f;
                            float num = dx * cc.z + dy * cc.w;
                            float den = dn2 * cn + 1e-8f;
                            float ang = 1.f - fabsf(num / den);
                            float ss = dy + nv + ang;
                            a0 = dy + ss; a1 = nv + ss; a2 = ang + ss;
                        }
                    }
                    av[d * 3] = a0; av[d * 3 + 1] = a1; av[d * 3 + 2] = a2;
                }
#pragma unroll
                for (int o = 0; o < 64; o++) {
                    float a = b0s[o];
#pragma unroll
                    for (int kc = 0; kc < 9; kc++)
                        a = fmaf(w0s[kc * 64 + o], av[kc], a);
                    r[o] = fmaxf(a, 0.f);
                }
            }
            if (padrow) {
#pragma unroll
                for (int o = 0; o < 64; o++) r[o] = 0.f;
            }

            // ---- conv layers 1 and 2 ----
#pragma unroll 1
            for (int L = 0; L < 2; L++) {
                const float* bias = L ? b2s : b1s;
                float s = 0.f;
#pragma unroll
                for (int o = 0; o < 64; o++) s += r[o];
                build_x(xr, r, s, m);
                BAR_ARRIVE(rdy, 384);
                BAR_SYNC(dn, 384);
#pragma unroll
                for (int i = 0; i < 16; i++) {
                    float4 y = *(const float4*)(xr + (size_t)(m * 68 + i * 4) * 4);
                    r[4 * i + 0] += fmaxf(y.x + bias[4 * i + 0], 0.f);
                    r[4 * i + 1] += fmaxf(y.y + bias[4 * i + 1], 0.f);
                    r[4 * i + 2] += fmaxf(y.z + bias[4 * i + 2], 0.f);
                    r[4 * i + 3] += fmaxf(y.w + bias[4 * i + 3], 0.f);
                }
                if (padrow) {
#pragma unroll
                    for (int o = 0; o < 64; o++) r[o] = 0.f;
                }
                BAR_SYNC(ib, 128);   // Y reads done before next X build
            }

            // ---- MLP half ----
            build_x(xr, r, 0.f, m);
            BAR_ARRIVE(rdy, 384);
            BAR_SYNC(dn, 384);
            {
                const int g = gbase + gi;
                const bool wr = live && !padrow && (g < ngroups);
                float* og = out + (size_t)g * 1152 + (prow - 1) * 128;
                if (phase == 0) {
                    if (wr) {
#pragma unroll
                        for (int i = 0; i < 16; i++) {
                            float4 y = *(const float4*)(xr + (size_t)(m * 68 + i * 4) * 4);
                            y.x += mbs[4 * i + 0]; y.y += mbs[4 * i + 1];
                            y.z += mbs[4 * i + 2]; y.w += mbs[4 * i + 3];
                            *(float4*)(og + 4 * i) = y;
                        }
                        const float4* fs = (const float4*)(feats + (size_t)g * 576 + (prow - 1) * 64);
                        float4* od = (float4*)(og + 64);
#pragma unroll
                        for (int q2 = 0; q2 < 16; q2++) od[q2] = fs[q2];
                    }
                } else {
                    if (wr) {
#pragma unroll
                        for (int i = 0; i < 16; i++) {
                            float4 y = *(const float4*)(xr + (size_t)(m * 68 + i * 4) * 4);
                            float4 o4 = *(const float4*)(og + 4 * i);
                            o4.x = fmaxf(o4.x + y.x, 0.f);
                            o4.y = fmaxf(o4.y + y.y, 0.f);
                            o4.z = fmaxf(o4.z + y.z, 0.f);
                            o4.w = fmaxf(o4.w + y.w, 0.f);
                            *(float4*)(og + 4 * i) = o4;
                        }
                    }
                }
            }
            BAR_SYNC(ib, 128);       // Y reads done before next tile's X build
        }
    }
}

extern "C" void kernel_launch(void* const* d_in, const int* in_sizes, int n_in,
                              void* d_out, int out_size)
{
    const float* pc    = (const float*)d_in[0];
    const float* feats = (const float*)d_in[1];
    // 2..13 = pos_* / rel_* (dead: pos_e/rel_e discarded by the reference)
    const float* nw0 = (const float*)d_in[14];
    const float* nb0 = (const float*)d_in[15];
    const float* nw1 = (const float*)d_in[16];
    const float* nb1 = (const float*)d_in[17];
    const float* nw2 = (const float*)d_in[18];
    const float* nb2 = (const float*)d_in[19];
    const float* aw0 = (const float*)d_in[20];
    const float* ab0 = (const float*)d_in[21];
    const float* aw1 = (const float*)d_in[22];
    const float* ab1 = (const float*)d_in[23];
    const float* aw2 = (const float*)d_in[24];
    const float* ab2 = (const float*)d_in[25];
    const float* mw  = (const float*)d_in[26];
    const float* mb  = (const float*)d_in[27];

    const int ngroups = in_sizes[0] / 36;
    const int ntiles = (ngroups + 10) / 11;
    const int grid = 148;
    const int nit = (ntiles + 2 * grid - 1) / (2 * grid);

    cudaFuncSetAttribute(locse_ws, cudaFuncAttributeMaxDynamicSharedMemorySize,
                         SMEM_TOT);

    locse_ws<<<grid, 512, SMEM_TOT>>>(0, pc, feats, nw0, 192, nb0,
                                      nw1, nb1, nw2, nb2, mw, mb,
                                      (float*)d_out, ngroups, ntiles, nit);
    locse_ws<<<grid, 512, SMEM_TOT>>>(1, pc, feats, aw0, 576, ab0,
                                      aw1, ab1, aw2, ab2, mw, nullptr,
                                      (float*)d_out, ngroups, ntiles, nit);
}